// round 6
// baseline (speedup 1.0000x reference)
#include <cuda_runtime.h>
#include <math.h>

// ---------------- problem constants ----------------
#define BA    8192      // B*A rows
#define AGN   8         // agents
#define EDIM  64
#define HDIM  512
#define H3    1536
#define NAOUT 16
#define TM    128
#define TN    128
#define TKK   16
#define MAXP  9216      // 8192 + 8*128 padding
#define MTILES (MAXP/TM) // 72

// ---------------- scratch (static device memory; no allocs) ----------------
__device__ float g_wm1[AGN*HDIM*EDIM];
__device__ float g_wm2[AGN*HDIM*HDIM];
__device__ float g_wm3[AGN*HDIM*HDIM];
__device__ float g_wm4[AGN*NAOUT*HDIM];
__device__ float g_xp [MAXP*EDIM];
__device__ float g_hp [MAXP*HDIM];
__device__ float g_y1 [MAXP*HDIM];
__device__ float g_gi [MAXP*H3];
__device__ float g_gh [MAXP*H3];
__device__ float g_hn [MAXP*HDIM];
__device__ float g_q2 [MAXP*HDIM];
__device__ float g_q3 [MAXP*HDIM];
__device__ int   g_perm[MAXP];
__device__ int   g_counts[AGN];
__device__ int   g_cursor[AGN];
__device__ int   g_segstart[AGN];
__device__ int   g_tile_agent[MTILES];

// ---------------- grouping kernels ----------------
__global__ void init_kernel() {
    int i = blockIdx.x * blockDim.x + threadIdx.x;
    if (i < MAXP) g_perm[i] = -1;
    if (i < AGN) { g_counts[i] = 0; g_cursor[i] = 0; }
}

__global__ void count_kernel(const int* __restrict__ ids) {
    int i = blockIdx.x * blockDim.x + threadIdx.x;
    if (i < BA) atomicAdd(&g_counts[ids[i]], 1);
}

__global__ void offsets_kernel() {
    if (threadIdx.x == 0) {
        int off = 0;
        for (int a = 0; a < AGN; a++) {
            g_segstart[a] = off;
            off += ((g_counts[a] + TM - 1) / TM) * TM;
        }
        for (int t = 0; t < MTILES; t++) {
            int r = t * TM;
            int ag = 0;
            for (int a = 1; a < AGN; a++)
                if (r >= g_segstart[a]) ag = a;
            g_tile_agent[t] = ag;
        }
    }
}

__global__ void scatter_kernel(const int* __restrict__ ids) {
    int i = blockIdx.x * blockDim.x + threadIdx.x;
    if (i < BA) {
        int a = ids[i];
        int pos = g_segstart[a] + atomicAdd(&g_cursor[a], 1);
        g_perm[pos] = i;
    }
}

__global__ void gather_kernel(const float* __restrict__ x, const float* __restrict__ h) {
    int pos = blockIdx.x;
    int n = g_perm[pos];
    float4* xp = (float4*)(g_xp + (size_t)pos * EDIM);
    float4* hp = (float4*)(g_hp + (size_t)pos * HDIM);
    if (n >= 0) {
        const float4* xs = (const float4*)(x + (size_t)n * EDIM);
        const float4* hs = (const float4*)(h + (size_t)n * HDIM);
        for (int v = threadIdx.x; v < EDIM/4; v += blockDim.x) xp[v] = xs[v];
        for (int v = threadIdx.x; v < HDIM/4; v += blockDim.x) hp[v] = hs[v];
    } else {
        float4 z = make_float4(0.f, 0.f, 0.f, 0.f);
        for (int v = threadIdx.x; v < EDIM/4; v += blockDim.x) xp[v] = z;
        for (int v = threadIdx.x; v < HDIM/4; v += blockDim.x) hp[v] = z;
    }
}

// ---------------- masked-weight precompute ----------------
// layer: 0=fc1 (O=H,G=E/4), 1=fc2, 2=fc3 (O=H,G=H/4), 3=fc4 (O=NA,G=H/4)
__global__ void mask_kernel(const float* __restrict__ alpha, const float* __restrict__ w,
                            int layer, int O, int G) {
    int idx = blockIdx.x * blockDim.x + threadIdx.x;
    int total = AGN * O * G;
    if (idx >= total) return;
    float* wm = (layer == 0) ? g_wm1 : (layer == 1) ? g_wm2 : (layer == 2) ? g_wm3 : g_wm4;
    int g = idx % G;
    int o = (idx / G) % O;
    int a = idx / (G * O);
    const float* al = alpha + (size_t)idx * 6;
    float l0 = al[0], l1 = al[1], l2 = al[2], l3 = al[3], l4 = al[4], l5 = al[5];
    float mx = fmaxf(fmaxf(fmaxf(l0, l1), fmaxf(l2, l3)), fmaxf(l4, l5));
    float e0 = expf((l0 - mx) * 0.2f);
    float e1 = expf((l1 - mx) * 0.2f);
    float e2 = expf((l2 - mx) * 0.2f);
    float e3 = expf((l3 - mx) * 0.2f);
    float e4 = expf((l4 - mx) * 0.2f);
    float e5 = expf((l5 - mx) * 0.2f);
    float inv = 1.f / (e0 + e1 + e2 + e3 + e4 + e5);
    // PATTERNS columns: k0:{p0,p1,p2} k1:{p0,p3,p4} k2:{p1,p3,p5} k3:{p2,p4,p5}
    float m0 = (e0 + e1 + e2) * inv;
    float m1 = (e0 + e3 + e4) * inv;
    float m2 = (e1 + e3 + e5) * inv;
    float m3 = (e2 + e4 + e5) * inv;
    int I = G * 4;
    const float* wr = w + (size_t)o * I + g * 4;
    float* wo = wm + ((size_t)a * O + o) * I + g * 4;
    wo[0] = wr[0] * m0;
    wo[1] = wr[1] * m1;
    wo[2] = wr[2] * m2;
    wo[3] = wr[3] * m3;
}

// ---------------- tiled fp32 GEMM: Y[m,n] = X[m,:] . W[agent][n,:] + bias ----------------
// xsel: 0=g_xp 1=g_y1 2=g_hp 3=g_hn 4=g_q2
// wsel: 0=g_wm1 1=g_wm2 2=g_wm3  (-1 => Wext, shared weights)
// ysel: 0=g_y1 1=g_gi 2=g_gh 3=g_q2 4=g_q3
__global__ __launch_bounds__(256, 2)
void gemm_kernel(int xsel, const float* __restrict__ Wext, int wsel, long wStride,
                 const float* __restrict__ bias, int ysel, int K, int N, int doRelu) {
    __shared__ float As[TKK][TM];
    __shared__ float Bs[TKK][TN];

    const float* X = (xsel == 0) ? g_xp : (xsel == 1) ? g_y1 : (xsel == 2) ? g_hp
                   : (xsel == 3) ? g_hn : g_q2;
    const float* W = (wsel == 0) ? g_wm1 : (wsel == 1) ? g_wm2 : (wsel == 2) ? g_wm3 : Wext;
    float* Y = (ysel == 0) ? g_y1 : (ysel == 1) ? g_gi : (ysel == 2) ? g_gh
             : (ysel == 3) ? g_q2 : g_q3;

    const int tile_n = blockIdx.x, tile_m = blockIdx.y;
    const int agent = g_tile_agent[tile_m];
    const float* Wb = W + (size_t)agent * wStride;
    const int tid = threadIdx.x;
    const int tx = tid & 15, ty = tid >> 4;
    const int lrow = tid & 127;
    const int lk4 = tid >> 7;  // 0 or 1

    const float* Xg = X + (size_t)(tile_m * TM + lrow) * K + lk4 * 4;
    const float* Wg = Wb + (size_t)(tile_n * TN + lrow) * K + lk4 * 4;

    float acc[8][8];
#pragma unroll
    for (int i = 0; i < 8; i++)
#pragma unroll
        for (int j = 0; j < 8; j++) acc[i][j] = 0.f;

    for (int k0 = 0; k0 < K; k0 += TKK) {
#pragma unroll
        for (int h = 0; h < 2; h++) {
            int kb = lk4 * 4 + h * 8;
            float4 va = *(const float4*)(Xg + k0 + h * 8);
            As[kb + 0][lrow] = va.x;
            As[kb + 1][lrow] = va.y;
            As[kb + 2][lrow] = va.z;
            As[kb + 3][lrow] = va.w;
            float4 vb = *(const float4*)(Wg + k0 + h * 8);
            Bs[kb + 0][lrow] = vb.x;
            Bs[kb + 1][lrow] = vb.y;
            Bs[kb + 2][lrow] = vb.z;
            Bs[kb + 3][lrow] = vb.w;
        }
        __syncthreads();
#pragma unroll
        for (int kk = 0; kk < TKK; kk++) {
            float4 a0 = *(const float4*)&As[kk][ty * 8];
            float4 a1 = *(const float4*)&As[kk][ty * 8 + 4];
            float4 b0 = *(const float4*)&Bs[kk][tx * 8];
            float4 b1 = *(const float4*)&Bs[kk][tx * 8 + 4];
            float av[8] = {a0.x, a0.y, a0.z, a0.w, a1.x, a1.y, a1.z, a1.w};
            float bv[8] = {b0.x, b0.y, b0.z, b0.w, b1.x, b1.y, b1.z, b1.w};
#pragma unroll
            for (int i = 0; i < 8; i++)
#pragma unroll
                for (int j = 0; j < 8; j++)
                    acc[i][j] += av[i] * bv[j];
        }
        __syncthreads();
    }

    const int m0 = tile_m * TM + ty * 8;
    const int n0 = tile_n * TN + tx * 8;
#pragma unroll
    for (int i = 0; i < 8; i++) {
        size_t base = (size_t)(m0 + i) * N + n0;
#pragma unroll
        for (int j = 0; j < 8; j++) {
            float v = acc[i][j] + bias[n0 + j];
            if (doRelu) v = fmaxf(v, 0.f);
            Y[base + j] = v;
        }
    }
}

// ---------------- GRU gate math + scatter of h ----------------
__global__ void gate_kernel(float* __restrict__ out_h) {
    int idx = blockIdx.x * blockDim.x + threadIdx.x;
    if (idx >= MAXP * HDIM) return;
    int pos = idx >> 9;       // / 512
    int j = idx & 511;
    size_t gb = (size_t)pos * H3 + j;
    float ir = g_gi[gb],            hr = g_gh[gb];
    float iz = g_gi[gb + HDIM],     hz = g_gh[gb + HDIM];
    float in_ = g_gi[gb + 2*HDIM],  hn_ = g_gh[gb + 2*HDIM];
    float r = 1.f / (1.f + expf(-(ir + hr)));
    float z = 1.f / (1.f + expf(-(iz + hz)));
    float nn = tanhf(in_ + r * hn_);
    float hprev = g_hp[(size_t)pos * HDIM + j];
    float hv = (1.f - z) * nn + z * hprev;
    g_hn[(size_t)pos * HDIM + j] = hv;
    int n = g_perm[pos];
    if (n >= 0) out_h[(size_t)n * HDIM + j] = hv;
}

// ---------------- fc4 (N=16) + scatter of q ----------------
__global__ void fc4_kernel(const float* __restrict__ b4, float* __restrict__ out_q) {
    int idx = blockIdx.x * blockDim.x + threadIdx.x;
    if (idx >= MAXP * NAOUT) return;
    int pos = idx / NAOUT, o = idx % NAOUT;
    int n = g_perm[pos];
    if (n < 0) return;
    int agent = g_tile_agent[pos / TM];
    const float4* x = (const float4*)(g_q3 + (size_t)pos * HDIM);
    const float4* w = (const float4*)(g_wm4 + ((size_t)agent * NAOUT + o) * HDIM);
    float s = 0.f;
#pragma unroll 8
    for (int k = 0; k < HDIM / 4; k++) {
        float4 xa = x[k], wa = w[k];
        s += xa.x * wa.x + xa.y * wa.y + xa.z * wa.z + xa.w * wa.w;
    }
    out_q[(size_t)n * NAOUT + o] = s + b4[o];
}

// ---------------- launch ----------------
extern "C" void kernel_launch(void* const* d_in, const int* in_sizes, int n_in,
                              void* d_out, int out_size) {
    const float* inputs = (const float*)d_in[0];
    const float* hidden = (const float*)d_in[1];
    const int*   ids    = (const int*)d_in[2];
    const float* fc1_w  = (const float*)d_in[3];
    const float* fc1_b  = (const float*)d_in[4];
    const float* fc1_a  = (const float*)d_in[5];
    const float* w_ih   = (const float*)d_in[6];
    const float* w_hh   = (const float*)d_in[7];
    const float* b_ih   = (const float*)d_in[8];
    const float* b_hh   = (const float*)d_in[9];
    const float* fc2_w  = (const float*)d_in[10];
    const float* fc2_b  = (const float*)d_in[11];
    const float* fc2_a  = (const float*)d_in[12];
    const float* fc3_w  = (const float*)d_in[13];
    const float* fc3_b  = (const float*)d_in[14];
    const float* fc3_a  = (const float*)d_in[15];
    const float* fc4_w  = (const float*)d_in[16];
    const float* fc4_b  = (const float*)d_in[17];
    const float* fc4_a  = (const float*)d_in[18];

    float* out   = (float*)d_out;
    float* out_q = out;                       // [BA, NAOUT]
    float* out_h = out + (size_t)BA * NAOUT;  // [BA, HDIM]

    // 1) agent grouping
    init_kernel<<<(MAXP + 255) / 256, 256>>>();
    count_kernel<<<(BA + 255) / 256, 256>>>(ids);
    offsets_kernel<<<1, 32>>>();
    scatter_kernel<<<(BA + 255) / 256, 256>>>(ids);

    // 2) masked weights (per agent)
    {
        int t1 = AGN * HDIM * (EDIM / 4);
        int t2 = AGN * HDIM * (HDIM / 4);
        int t4 = AGN * NAOUT * (HDIM / 4);
        mask_kernel<<<(t1 + 255) / 256, 256>>>(fc1_a, fc1_w, 0, HDIM, EDIM / 4);
        mask_kernel<<<(t2 + 255) / 256, 256>>>(fc2_a, fc2_w, 1, HDIM, HDIM / 4);
        mask_kernel<<<(t2 + 255) / 256, 256>>>(fc3_a, fc3_w, 2, HDIM, HDIM / 4);
        mask_kernel<<<(t4 + 255) / 256, 256>>>(fc4_a, fc4_w, 3, NAOUT, HDIM / 4);
    }

    // 3) gather permuted activations
    gather_kernel<<<MAXP, 128>>>(inputs, hidden);

    // 4) fc1 + relu : y1 = relu(xp @ wm1[a]^T + b1)
    gemm_kernel<<<dim3(HDIM / TN, MTILES), 256>>>(
        0, nullptr, 0, (long)HDIM * EDIM, fc1_b, 0, EDIM, HDIM, 1);

    // 5) GRU input/ hidden GEMMs (shared weights, stride 0)
    gemm_kernel<<<dim3(H3 / TN, MTILES), 256>>>(
        1, w_ih, -1, 0, b_ih, 1, HDIM, H3, 0);
    gemm_kernel<<<dim3(H3 / TN, MTILES), 256>>>(
        2, w_hh, -1, 0, b_hh, 2, HDIM, H3, 0);

    // 6) GRU gates -> hn (+ scatter h to output)
    gate_kernel<<<(MAXP * HDIM + 255) / 256, 256>>>(out_h);

    // 7) fc2 + relu, fc3 + relu
    gemm_kernel<<<dim3(HDIM / TN, MTILES), 256>>>(
        3, nullptr, 1, (long)HDIM * HDIM, fc2_b, 3, HDIM, HDIM, 1);
    gemm_kernel<<<dim3(HDIM / TN, MTILES), 256>>>(
        4, nullptr, 2, (long)HDIM * HDIM, fc3_b, 4, HDIM, HDIM, 1);

    // 8) fc4 (+ scatter q to output)
    fc4_kernel<<<(MAXP * NAOUT + 255) / 256, 256>>>(fc4_b, out_q);
}

// round 9
// speedup vs baseline: 2.4747x; 2.4747x over previous
#include <cuda_runtime.h>
#include <cuda_bf16.h>
#include <cstdint>
#include <math.h>

// ---------------- problem constants ----------------
#define BA    8192
#define AGN   8
#define EDIM  64
#define HDIM  512
#define H3    1536
#define NAOUT 16
#define TM    128
#define MAXP  9216
#define MTILES (MAXP/TM) // 72

// ---------------- PTX helpers ----------------
__device__ __forceinline__ uint32_t smem_u32(const void* p) {
    uint32_t a;
    asm("{ .reg .u64 t; cvta.to.shared.u64 t, %1; cvt.u32.u64 %0, t; }" : "=r"(a) : "l"(p));
    return a;
}
__device__ __forceinline__ void cp16(uint32_t saddr, const void* g) {
    asm volatile("{ .reg .u64 ga; cvta.to.global.u64 ga, %1;\n\t"
                 "cp.async.cg.shared.global [%0], [ga], 16; }"
                 :: "r"(saddr), "l"(g) : "memory");
}
#define CP_COMMIT() asm volatile("cp.async.commit_group;" ::: "memory")
#define CP_WAIT(n)  asm volatile("cp.async.wait_group %0;" :: "n"(n) : "memory")

__device__ __forceinline__ void ldmat_x4(uint32_t* r, uint32_t addr) {
    asm volatile("ldmatrix.sync.aligned.m8n8.x4.shared.b16 {%0,%1,%2,%3}, [%4];"
        : "=r"(r[0]), "=r"(r[1]), "=r"(r[2]), "=r"(r[3]) : "r"(addr));
}
__device__ __forceinline__ void mma16816(float* c, const uint32_t* a, const uint32_t* b) {
    asm volatile("mma.sync.aligned.m16n8k16.row.col.f32.bf16.bf16.f32 "
        "{%0,%1,%2,%3}, {%4,%5,%6,%7}, {%8,%9}, {%0,%1,%2,%3};"
        : "+f"(c[0]), "+f"(c[1]), "+f"(c[2]), "+f"(c[3])
        : "r"(a[0]), "r"(a[1]), "r"(a[2]), "r"(a[3]), "r"(b[0]), "r"(b[1]));
}

#define SWZ(bo) ((bo) ^ (((bo) >> 3) & 0x70))

__device__ __forceinline__ void split_bf16(float v, __nv_bfloat16& h, __nv_bfloat16& l) {
    h = __float2bfloat16(v);
    l = __float2bfloat16(v - __bfloat162float(h));
}

// ---------------- scratch (static device memory; no allocs) ----------------
__device__ __nv_bfloat16 g_w1h[AGN*HDIM*EDIM],  g_w1l[AGN*HDIM*EDIM];
__device__ __nv_bfloat16 g_w2h[AGN*HDIM*HDIM],  g_w2l[AGN*HDIM*HDIM];
__device__ __nv_bfloat16 g_w3h[AGN*HDIM*HDIM],  g_w3l[AGN*HDIM*HDIM];
__device__ __nv_bfloat16 g_wihh[H3*HDIM], g_wihl[H3*HDIM];
__device__ __nv_bfloat16 g_whhh[H3*HDIM], g_whhl[H3*HDIM];
__device__ float g_wm4[AGN*NAOUT*HDIM];
__device__ __nv_bfloat16 g_xh [MAXP*EDIM], g_xl [MAXP*EDIM];
__device__ __nv_bfloat16 g_hph[MAXP*HDIM], g_hpl[MAXP*HDIM];
__device__ __nv_bfloat16 g_y1h[MAXP*HDIM], g_y1l[MAXP*HDIM];
__device__ __nv_bfloat16 g_hnh[MAXP*HDIM], g_hnl[MAXP*HDIM];
__device__ __nv_bfloat16 g_q2h[MAXP*HDIM], g_q2l[MAXP*HDIM];
__device__ __nv_bfloat16 g_q3h[MAXP*HDIM], g_q3l[MAXP*HDIM];
__device__ float g_hp [MAXP*HDIM];
__device__ float g_gi [MAXP*H3];
__device__ float g_gh [MAXP*H3];
__device__ int   g_perm[MAXP];
__device__ int   g_counts[AGN];
__device__ int   g_cursor[AGN];
__device__ int   g_segstart[AGN];
__device__ int   g_tile_agent[MTILES];

// ---------------- grouping kernels ----------------
__global__ void init_kernel() {
    int i = blockIdx.x * blockDim.x + threadIdx.x;
    if (i < MAXP) g_perm[i] = -1;
    if (i < AGN) { g_counts[i] = 0; g_cursor[i] = 0; }
}

__global__ void count_kernel(const int* __restrict__ ids) {
    int i = blockIdx.x * blockDim.x + threadIdx.x;
    if (i < BA) atomicAdd(&g_counts[ids[i]], 1);
}

__global__ void offsets_kernel() {
    if (threadIdx.x == 0) {
        int off = 0;
        for (int a = 0; a < AGN; a++) {
            g_segstart[a] = off;
            off += ((g_counts[a] + TM - 1) / TM) * TM;
        }
        for (int t = 0; t < MTILES; t++) {
            int r = t * TM;
            int ag = 0;
            for (int a = 1; a < AGN; a++)
                if (r >= g_segstart[a]) ag = a;
            g_tile_agent[t] = ag;
        }
    }
}

__global__ void scatter_kernel(const int* __restrict__ ids) {
    int i = blockIdx.x * blockDim.x + threadIdx.x;
    if (i < BA) {
        int a = ids[i];
        int pos = g_segstart[a] + atomicAdd(&g_cursor[a], 1);
        g_perm[pos] = i;
    }
}

__global__ void gather_kernel(const float* __restrict__ x, const float* __restrict__ h) {
    int pos = blockIdx.x;
    int n = g_perm[pos];
    if (n >= 0) {
        for (int v = threadIdx.x; v < EDIM; v += blockDim.x) {
            float f = x[(size_t)n * EDIM + v];
            split_bf16(f, g_xh[(size_t)pos * EDIM + v], g_xl[(size_t)pos * EDIM + v]);
        }
        for (int v = threadIdx.x; v < HDIM; v += blockDim.x) {
            float f = h[(size_t)n * HDIM + v];
            g_hp[(size_t)pos * HDIM + v] = f;
            split_bf16(f, g_hph[(size_t)pos * HDIM + v], g_hpl[(size_t)pos * HDIM + v]);
        }
    } else {
        __nv_bfloat16 z = __float2bfloat16(0.f);
        for (int v = threadIdx.x; v < EDIM; v += blockDim.x) {
            g_xh[(size_t)pos * EDIM + v] = z; g_xl[(size_t)pos * EDIM + v] = z;
        }
        for (int v = threadIdx.x; v < HDIM; v += blockDim.x) {
            g_hp[(size_t)pos * HDIM + v] = 0.f;
            g_hph[(size_t)pos * HDIM + v] = z; g_hpl[(size_t)pos * HDIM + v] = z;
        }
    }
}

// ---------------- masked-weight precompute (writes bf16 hi/lo pairs) ----------------
__global__ void mask_kernel(const float* __restrict__ alpha, const float* __restrict__ w,
                            int layer, int O, int G) {
    int idx = blockIdx.x * blockDim.x + threadIdx.x;
    int total = AGN * O * G;
    if (idx >= total) return;
    int g = idx % G;
    int o = (idx / G) % O;
    int a = idx / (G * O);
    const float* al = alpha + (size_t)idx * 6;
    float l0 = al[0], l1 = al[1], l2 = al[2], l3 = al[3], l4 = al[4], l5 = al[5];
    float mx = fmaxf(fmaxf(fmaxf(l0, l1), fmaxf(l2, l3)), fmaxf(l4, l5));
    float e0 = expf((l0 - mx) * 0.2f);
    float e1 = expf((l1 - mx) * 0.2f);
    float e2 = expf((l2 - mx) * 0.2f);
    float e3 = expf((l3 - mx) * 0.2f);
    float e4 = expf((l4 - mx) * 0.2f);
    float e5 = expf((l5 - mx) * 0.2f);
    float inv = 1.f / (e0 + e1 + e2 + e3 + e4 + e5);
    float m0 = (e0 + e1 + e2) * inv;
    float m1 = (e0 + e3 + e4) * inv;
    float m2 = (e1 + e3 + e5) * inv;
    float m3 = (e2 + e4 + e5) * inv;
    int I = G * 4;
    const float* wr = w + (size_t)o * I + g * 4;
    float v0 = wr[0] * m0, v1 = wr[1] * m1, v2 = wr[2] * m2, v3 = wr[3] * m3;
    size_t base = ((size_t)a * O + o) * I + g * 4;
    if (layer == 3) {
        g_wm4[base + 0] = v0; g_wm4[base + 1] = v1;
        g_wm4[base + 2] = v2; g_wm4[base + 3] = v3;
    } else {
        __nv_bfloat16 *wh = (layer == 0) ? g_w1h : (layer == 1) ? g_w2h : g_w3h;
        __nv_bfloat16 *wl = (layer == 0) ? g_w1l : (layer == 1) ? g_w2l : g_w3l;
        split_bf16(v0, wh[base + 0], wl[base + 0]);
        split_bf16(v1, wh[base + 1], wl[base + 1]);
        split_bf16(v2, wh[base + 2], wl[base + 2]);
        split_bf16(v3, wh[base + 3], wl[base + 3]);
    }
}

// ---------------- GRU weight fp32 -> bf16 hi/lo ----------------
__global__ void conv_gru_w(const float* __restrict__ w_ih, const float* __restrict__ w_hh) {
    int idx = blockIdx.x * blockDim.x + threadIdx.x;
    const int NW = H3 * HDIM;
    if (idx < NW) {
        split_bf16(w_ih[idx], g_wihh[idx], g_wihl[idx]);
    } else if (idx < 2 * NW) {
        int j = idx - NW;
        split_bf16(w_hh[j], g_whhh[j], g_whhl[j]);
    }
}

// ---------------- mma.sync bf16x3 GEMM ----------------
// Y[m,n] = X[m,:] . W[agent][n,:] + bias ; X,W as bf16 (hi,lo) pairs.
// CTA tile 128x128, 8 warps of 32(M)x64(N). K chunk = 64.
#define STAGE_BYTES 65536
#define A_HI 0
#define A_LO 16384
#define B_HI 32768
#define B_LO 49152

__global__ __launch_bounds__(256, 1)
void gemm_tc(int xsel, int wsel, long wStride, const float* __restrict__ bias,
             int ysel, int K, int N, int doRelu) {
    extern __shared__ char dsm[];

    const __nv_bfloat16 *Xh, *Xl, *Wh, *Wl;
    switch (xsel) {
        case 0: Xh = g_xh;  Xl = g_xl;  break;
        case 1: Xh = g_y1h; Xl = g_y1l; break;
        case 2: Xh = g_hph; Xl = g_hpl; break;
        case 3: Xh = g_hnh; Xl = g_hnl; break;
        default: Xh = g_q2h; Xl = g_q2l; break;
    }
    switch (wsel) {
        case 0: Wh = g_w1h;  Wl = g_w1l;  break;
        case 1: Wh = g_w2h;  Wl = g_w2l;  break;
        case 2: Wh = g_w3h;  Wl = g_w3l;  break;
        case 3: Wh = g_wihh; Wl = g_wihl; break;
        default: Wh = g_whhh; Wl = g_whhl; break;
    }
    float* Yf = nullptr;
    __nv_bfloat16 *Yh = nullptr, *Yl = nullptr;
    switch (ysel) {
        case 0: Yh = g_y1h; Yl = g_y1l; break;
        case 1: Yf = g_gi; break;
        case 2: Yf = g_gh; break;
        case 3: Yh = g_q2h; Yl = g_q2l; break;
        default: Yh = g_q3h; Yl = g_q3l; break;
    }

    const int tile_n = blockIdx.x, tile_m = blockIdx.y;
    const int agent = g_tile_agent[tile_m];
    Wh += (size_t)agent * wStride;
    Wl += (size_t)agent * wStride;

    const int tid = threadIdx.x;
    const int wid = tid >> 5;
    const int lane = tid & 31;
    const int warp_m = (wid & 3) * 32;   // M offset within CTA tile
    const int warp_n = (wid >> 2) * 64;  // N offset within CTA tile

    uint32_t sb = smem_u32(dsm);
    uint32_t tb = (sb + 1023u) & ~1023u;

    const __nv_bfloat16* srcs[4] = {Xh, Xl, Wh, Wl};
    const int C = K >> 6;

    // ldmatrix per-lane base byte offsets (within a 128x64 bf16 tile, 128B rows)
    // A atoms (16x16): lanes 0-15 rows, lanes 16-31 same rows, k+8
    const uint32_t a_bo0 = (uint32_t)(warp_m + (lane & 15)) * 128 + ((lane >> 4) << 4);
    // B atom-pairs: rows = n, lanes {0-7,16-23} -> n, n+8 ; lanes {8-15,24-31} -> k+8
    const uint32_t b_bo0 = (uint32_t)(warp_n + (lane & 7) + ((lane >> 4) << 3)) * 128
                         + (((lane >> 3) & 1) << 4);

    float acc[2][8][4];
#pragma unroll
    for (int mi = 0; mi < 2; mi++)
#pragma unroll
        for (int ni = 0; ni < 8; ni++)
#pragma unroll
            for (int j = 0; j < 4; j++) acc[mi][ni][j] = 0.f;

    auto load_stage = [&](int c) {
        const int s = c & 1;
        const uint32_t stb = tb + s * STAGE_BYTES;
        const int k0 = c << 6;
#pragma unroll
        for (int t = 0; t < 4; t++) {
            const __nv_bfloat16* src = srcs[t];
            const int row0 = (t < 2) ? tile_m * TM : tile_n * 128;
            const uint32_t tbase = stb + t * 16384;
#pragma unroll
            for (int it = 0; it < 4; it++) {
                int seg = tid + it * 256;
                int row = seg >> 3, sc = seg & 7;
                const void* g = src + (size_t)(row0 + row) * K + k0 + sc * 8;
                uint32_t bo = (uint32_t)(row * 128 + sc * 16);
                cp16(tbase + SWZ(bo), g);
            }
        }
        CP_COMMIT();
    };

    load_stage(0);

    for (int c = 0; c < C; c++) {
        if (c + 1 < C) { load_stage(c + 1); CP_WAIT(1); }
        else           { CP_WAIT(0); }
        __syncthreads();

        const uint32_t stb = tb + (c & 1) * STAGE_BYTES;
        const uint32_t aHi = stb + A_HI, aLo = stb + A_LO;
        const uint32_t bHi = stb + B_HI, bLo = stb + B_LO;

#pragma unroll
        for (int kk = 0; kk < 4; kk++) {
            uint32_t ah[2][4], al2[2][4], bh[4][4], bl[4][4];
#pragma unroll
            for (int mi = 0; mi < 2; mi++) {
                uint32_t bo = a_bo0 + mi * 2048 + kk * 32;
                uint32_t sw = SWZ(bo);
                ldmat_x4(ah[mi], aHi + sw);
                ldmat_x4(al2[mi], aLo + sw);
            }
#pragma unroll
            for (int pi = 0; pi < 4; pi++) {
                uint32_t bo = b_bo0 + pi * 2048 + kk * 32;
                uint32_t sw = SWZ(bo);
                ldmat_x4(bh[pi], bHi + sw);
                ldmat_x4(bl[pi], bLo + sw);
            }
#pragma unroll
            for (int mi = 0; mi < 2; mi++) {
#pragma unroll
                for (int pi = 0; pi < 4; pi++) {
                    mma16816(acc[mi][pi * 2 + 0], ah[mi],  &bh[pi][0]);
                    mma16816(acc[mi][pi * 2 + 1], ah[mi],  &bh[pi][2]);
                    mma16816(acc[mi][pi * 2 + 0], ah[mi],  &bl[pi][0]);
                    mma16816(acc[mi][pi * 2 + 1], ah[mi],  &bl[pi][2]);
                    mma16816(acc[mi][pi * 2 + 0], al2[mi], &bh[pi][0]);
                    mma16816(acc[mi][pi * 2 + 1], al2[mi], &bh[pi][2]);
                }
            }
        }
        __syncthreads();
    }

    // epilogue: fragment (g = lane/4 row, tg = lane%4 col-pair)
    const int g = lane >> 2, tg = lane & 3;
#pragma unroll
    for (int mi = 0; mi < 2; mi++) {
        const int m_lo = tile_m * TM + warp_m + mi * 16 + g;
#pragma unroll
        for (int ni = 0; ni < 8; ni++) {
            const int n = tile_n * 128 + warp_n + ni * 8 + tg * 2;
            const float b0 = bias[n], b1 = bias[n + 1];
            float* c = acc[mi][ni];
#pragma unroll
            for (int half = 0; half < 2; half++) {
                const int m = m_lo + half * 8;
                float v0 = c[half * 2 + 0] + b0;
                float v1 = c[half * 2 + 1] + b1;
                if (doRelu) { v0 = fmaxf(v0, 0.f); v1 = fmaxf(v1, 0.f); }
                const size_t base = (size_t)m * N + n;
                if (Yf) {
                    float2 f2 = make_float2(v0, v1);
                    *(float2*)(Yf + base) = f2;
                } else {
                    __nv_bfloat16 h0, l0, h1, l1;
                    split_bf16(v0, h0, l0);
                    split_bf16(v1, h1, l1);
                    __nv_bfloat162 ph, pl;
                    ph.x = h0; ph.y = h1;
                    pl.x = l0; pl.y = l1;
                    *(__nv_bfloat162*)(Yh + base) = ph;
                    *(__nv_bfloat162*)(Yl + base) = pl;
                }
            }
        }
    }
}

// ---------------- GRU gate math + scatter of h ----------------
__global__ void gate_kernel(float* __restrict__ out_h) {
    int idx = blockIdx.x * blockDim.x + threadIdx.x;
    if (idx >= MAXP * HDIM) return;
    int pos = idx >> 9;
    int j = idx & 511;
    size_t gb = (size_t)pos * H3 + j;
    float ir = g_gi[gb],            hr = g_gh[gb];
    float iz = g_gi[gb + HDIM],     hz = g_gh[gb + HDIM];
    float in_ = g_gi[gb + 2*HDIM],  hn_ = g_gh[gb + 2*HDIM];
    float r = 1.f / (1.f + expf(-(ir + hr)));
    float z = 1.f / (1.f + expf(-(iz + hz)));
    float nn = tanhf(in_ + r * hn_);
    float hprev = g_hp[(size_t)pos * HDIM + j];
    float hv = (1.f - z) * nn + z * hprev;
    split_bf16(hv, g_hnh[(size_t)pos * HDIM + j], g_hnl[(size_t)pos * HDIM + j]);
    int n = g_perm[pos];
    if (n >= 0) out_h[(size_t)n * HDIM + j] = hv;
}

// ---------------- fc4 (N=16) + scatter of q ----------------
__global__ void fc4_kernel(const float* __restrict__ b4, float* __restrict__ out_q) {
    int idx = blockIdx.x * blockDim.x + threadIdx.x;
    if (idx >= MAXP * NAOUT) return;
    int pos = idx / NAOUT, o = idx % NAOUT;
    int n = g_perm[pos];
    if (n < 0) return;
    int agent = g_tile_agent[pos / TM];
    const __nv_bfloat16* xh = g_q3h + (size_t)pos * HDIM;
    const __nv_bfloat16* xl = g_q3l + (size_t)pos * HDIM;
    const float4* w = (const float4*)(g_wm4 + ((size_t)agent * NAOUT + o) * HDIM);
    float s = 0.f;
#pragma unroll 4
    for (int k = 0; k < HDIM / 4; k++) {
        float4 wa = w[k];
        float x0 = __bfloat162float(xh[k*4+0]) + __bfloat162float(xl[k*4+0]);
        float x1 = __bfloat162float(xh[k*4+1]) + __bfloat162float(xl[k*4+1]);
        float x2 = __bfloat162float(xh[k*4+2]) + __bfloat162float(xl[k*4+2]);
        float x3 = __bfloat162float(xh[k*4+3]) + __bfloat162float(xl[k*4+3]);
        s += x0 * wa.x + x1 * wa.y + x2 * wa.z + x3 * wa.w;
    }
    out_q[(size_t)n * NAOUT + o] = s + b4[o];
}

// ---------------- launch ----------------
extern "C" void kernel_launch(void* const* d_in, const int* in_sizes, int n_in,
                              void* d_out, int out_size) {
    const float* inputs = (const float*)d_in[0];
    const float* hidden = (const float*)d_in[1];
    const int*   ids    = (const int*)d_in[2];
    const float* fc1_w  = (const float*)d_in[3];
    const float* fc1_b  = (const float*)d_in[4];
    const float* fc1_a  = (const float*)d_in[5];
    const float* w_ih   = (const float*)d_in[6];
    const float* w_hh   = (const float*)d_in[7];
    const float* b_ih   = (const float*)d_in[8];
    const float* b_hh   = (const float*)d_in[9];
    const float* fc2_w  = (const float*)d_in[10];
    const float* fc2_b  = (const float*)d_in[11];
    const float* fc2_a  = (const float*)d_in[12];
    const float* fc3_w  = (const float*)d_in[13];
    const float* fc3_b  = (const float*)d_in[14];
    const float* fc3_a  = (const float*)d_in[15];
    const float* fc4_w  = (const float*)d_in[16];
    const float* fc4_b  = (const float*)d_in[17];
    const float* fc4_a  = (const float*)d_in[18];

    float* out   = (float*)d_out;
    float* out_q = out;
    float* out_h = out + (size_t)BA * NAOUT;

    const int SMEM_GEMM = 2 * STAGE_BYTES + 1024;
    cudaFuncSetAttribute(gemm_tc, cudaFuncAttributeMaxDynamicSharedMemorySize, SMEM_GEMM);

    // 1) agent grouping
    init_kernel<<<(MAXP + 255) / 256, 256>>>();
    count_kernel<<<(BA + 255) / 256, 256>>>(ids);
    offsets_kernel<<<1, 32>>>();
    scatter_kernel<<<(BA + 255) / 256, 256>>>(ids);

    // 2) masked weights (bf16 hi/lo) + GRU weight conversion
    {
        int t1 = AGN * HDIM * (EDIM / 4);
        int t2 = AGN * HDIM * (HDIM / 4);
        int t4 = AGN * NAOUT * (HDIM / 4);
        mask_kernel<<<(t1 + 255) / 256, 256>>>(fc1_a, fc1_w, 0, HDIM, EDIM / 4);
        mask_kernel<<<(t2 + 255) / 256, 256>>>(fc2_a, fc2_w, 1, HDIM, HDIM / 4);
        mask_kernel<<<(t2 + 255) / 256, 256>>>(fc3_a, fc3_w, 2, HDIM, HDIM / 4);
        mask_kernel<<<(t4 + 255) / 256, 256>>>(fc4_a, fc4_w, 3, NAOUT, HDIM / 4);
        conv_gru_w<<<(2 * H3 * HDIM + 255) / 256, 256>>>(w_ih, w_hh);
    }

    // 3) gather permuted activations (bf16 pairs + fp32 hp)
    gather_kernel<<<MAXP, 128>>>(inputs, hidden);

    // 4) fc1 + relu -> y1 pair
    gemm_tc<<<dim3(HDIM / 128, MTILES), 256, SMEM_GEMM>>>(
        0, 0, (long)HDIM * EDIM, fc1_b, 0, EDIM, HDIM, 1);

    // 5) GRU GEMMs (shared weights, stride 0) -> gi/gh fp32
    gemm_tc<<<dim3(H3 / 128, MTILES), 256, SMEM_GEMM>>>(
        1, 3, 0, b_ih, 1, HDIM, H3, 0);
    gemm_tc<<<dim3(H3 / 128, MTILES), 256, SMEM_GEMM>>>(
        2, 4, 0, b_hh, 2, HDIM, H3, 0);

    // 6) GRU gates -> hn pair (+ scatter h)
    gate_kernel<<<(MAXP * HDIM + 255) / 256, 256>>>(out_h);

    // 7) fc2 + relu -> q2 pair ; fc3 + relu -> q3 pair
    gemm_tc<<<dim3(HDIM / 128, MTILES), 256, SMEM_GEMM>>>(
        3, 1, (long)HDIM * HDIM, fc2_b, 3, HDIM, HDIM, 1);
    gemm_tc<<<dim3(HDIM / 128, MTILES), 256, SMEM_GEMM>>>(
        4, 2, (long)HDIM * HDIM, fc3_b, 4, HDIM, HDIM, 1);

    // 8) fc4 (+ scatter q)
    fc4_kernel<<<(MAXP * NAOUT + 255) / 256, 256>>>(fc4_b, out_q);
}

// round 10
// speedup vs baseline: 3.1848x; 1.2869x over previous
#include <cuda_runtime.h>
#include <cuda_bf16.h>
#include <cstdint>
#include <math.h>

// ---------------- problem constants ----------------
#define BA    8192
#define AGN   8
#define EDIM  64
#define HDIM  512
#define H3    1536
#define NAOUT 16
#define NPAD4 128      // fc4 N padded to 128
#define TM    128
#define MAXP  9216
#define MTILES (MAXP/TM) // 72

// ---------------- PTX helpers ----------------
__device__ __forceinline__ uint32_t smem_u32(const void* p) {
    uint32_t a;
    asm("{ .reg .u64 t; cvta.to.shared.u64 t, %1; cvt.u32.u64 %0, t; }" : "=r"(a) : "l"(p));
    return a;
}
__device__ __forceinline__ void cp16(uint32_t saddr, const void* g) {
    asm volatile("{ .reg .u64 ga; cvta.to.global.u64 ga, %1;\n\t"
                 "cp.async.cg.shared.global [%0], [ga], 16; }"
                 :: "r"(saddr), "l"(g) : "memory");
}
#define CP_COMMIT() asm volatile("cp.async.commit_group;" ::: "memory")
#define CP_WAIT(n)  asm volatile("cp.async.wait_group %0;" :: "n"(n) : "memory")

__device__ __forceinline__ void ldmat_x4(uint32_t* r, uint32_t addr) {
    asm volatile("ldmatrix.sync.aligned.m8n8.x4.shared.b16 {%0,%1,%2,%3}, [%4];"
        : "=r"(r[0]), "=r"(r[1]), "=r"(r[2]), "=r"(r[3]) : "r"(addr));
}
__device__ __forceinline__ void mma16816(float* c, const uint32_t* a, const uint32_t* b) {
    asm volatile("mma.sync.aligned.m16n8k16.row.col.f32.bf16.bf16.f32 "
        "{%0,%1,%2,%3}, {%4,%5,%6,%7}, {%8,%9}, {%0,%1,%2,%3};"
        : "+f"(c[0]), "+f"(c[1]), "+f"(c[2]), "+f"(c[3])
        : "r"(a[0]), "r"(a[1]), "r"(a[2]), "r"(a[3]), "r"(b[0]), "r"(b[1]));
}
__device__ __forceinline__ float tfast(float x) {
    float y; asm("tanh.approx.f32 %0, %1;" : "=f"(y) : "f"(x)); return y;
}
__device__ __forceinline__ float sigf(float x) { return 0.5f * tfast(0.5f * x) + 0.5f; }

#define SWZ(bo) ((bo) ^ (((bo) >> 3) & 0x70))

__device__ __forceinline__ void split_bf16(float v, __nv_bfloat16& h, __nv_bfloat16& l) {
    h = __float2bfloat16(v);
    l = __float2bfloat16(v - __bfloat162float(h));
}

// ---------------- scratch (static device memory; no allocs) ----------------
__device__ __nv_bfloat16 g_w1h[AGN*HDIM*EDIM],  g_w1l[AGN*HDIM*EDIM];
__device__ __nv_bfloat16 g_w2h[AGN*HDIM*HDIM],  g_w2l[AGN*HDIM*HDIM];
__device__ __nv_bfloat16 g_w3h[AGN*HDIM*HDIM],  g_w3l[AGN*HDIM*HDIM];
__device__ __nv_bfloat16 g_w4h[AGN*NPAD4*HDIM], g_w4l[AGN*NPAD4*HDIM];
__device__ __nv_bfloat16 g_wihh[H3*HDIM], g_wihl[H3*HDIM];
__device__ __nv_bfloat16 g_whhh[H3*HDIM], g_whhl[H3*HDIM];
__device__ __nv_bfloat16 g_xh [MAXP*EDIM], g_xl [MAXP*EDIM];
__device__ __nv_bfloat16 g_hph[MAXP*HDIM], g_hpl[MAXP*HDIM];
__device__ __nv_bfloat16 g_y1h[MAXP*HDIM], g_y1l[MAXP*HDIM];
__device__ __nv_bfloat16 g_hnh[MAXP*HDIM], g_hnl[MAXP*HDIM];
__device__ __nv_bfloat16 g_q2h[MAXP*HDIM], g_q2l[MAXP*HDIM];
__device__ __nv_bfloat16 g_q3h[MAXP*HDIM], g_q3l[MAXP*HDIM];
__device__ float g_hp [MAXP*HDIM];
__device__ float g_gi [MAXP*H3];
__device__ float g_gh [MAXP*H3];
__device__ int   g_perm[MAXP];
__device__ int   g_counts[AGN];
__device__ int   g_cursor[AGN];
__device__ int   g_segstart[AGN];
__device__ int   g_tile_agent[MTILES];

// ---------------- grouping kernels ----------------
__global__ void init_kernel() {
    int i = blockIdx.x * blockDim.x + threadIdx.x;
    if (i < MAXP) g_perm[i] = -1;
    if (i < AGN) { g_counts[i] = 0; g_cursor[i] = 0; }
}

__global__ void count_kernel(const int* __restrict__ ids) {
    int i = blockIdx.x * blockDim.x + threadIdx.x;
    if (i < BA) atomicAdd(&g_counts[ids[i]], 1);
}

__global__ void offsets_kernel() {
    if (threadIdx.x == 0) {
        int off = 0;
        for (int a = 0; a < AGN; a++) {
            g_segstart[a] = off;
            off += ((g_counts[a] + TM - 1) / TM) * TM;
        }
        for (int t = 0; t < MTILES; t++) {
            int r = t * TM;
            int ag = 0;
            for (int a = 1; a < AGN; a++)
                if (r >= g_segstart[a]) ag = a;
            g_tile_agent[t] = ag;
        }
    }
}

__global__ void scatter_kernel(const int* __restrict__ ids) {
    int i = blockIdx.x * blockDim.x + threadIdx.x;
    if (i < BA) {
        int a = ids[i];
        int pos = g_segstart[a] + atomicAdd(&g_cursor[a], 1);
        g_perm[pos] = i;
    }
}

__global__ void gather_kernel(const float* __restrict__ x, const float* __restrict__ h) {
    int pos = blockIdx.x;
    int n = g_perm[pos];
    if (n >= 0) {
        for (int v = threadIdx.x; v < EDIM / 4; v += blockDim.x) {
            float4 f = *(const float4*)(x + (size_t)n * EDIM + v * 4);
            __nv_bfloat16 h0, l0, h1, l1, h2, l2, h3, l3;
            split_bf16(f.x, h0, l0); split_bf16(f.y, h1, l1);
            split_bf16(f.z, h2, l2); split_bf16(f.w, h3, l3);
            __nv_bfloat162* xhp = (__nv_bfloat162*)(g_xh + (size_t)pos * EDIM + v * 4);
            __nv_bfloat162* xlp = (__nv_bfloat162*)(g_xl + (size_t)pos * EDIM + v * 4);
            xhp[0] = {h0, h1}; xhp[1] = {h2, h3};
            xlp[0] = {l0, l1}; xlp[1] = {l2, l3};
        }
        for (int v = threadIdx.x; v < HDIM / 4; v += blockDim.x) {
            float4 f = *(const float4*)(h + (size_t)n * HDIM + v * 4);
            *(float4*)(g_hp + (size_t)pos * HDIM + v * 4) = f;
            __nv_bfloat16 h0, l0, h1, l1, h2, l2, h3, l3;
            split_bf16(f.x, h0, l0); split_bf16(f.y, h1, l1);
            split_bf16(f.z, h2, l2); split_bf16(f.w, h3, l3);
            __nv_bfloat162* hhp = (__nv_bfloat162*)(g_hph + (size_t)pos * HDIM + v * 4);
            __nv_bfloat162* hlp = (__nv_bfloat162*)(g_hpl + (size_t)pos * HDIM + v * 4);
            hhp[0] = {h0, h1}; hhp[1] = {h2, h3};
            hlp[0] = {l0, l1}; hlp[1] = {l2, l3};
        }
    } else {
        __nv_bfloat162 z2 = {__float2bfloat16(0.f), __float2bfloat16(0.f)};
        for (int v = threadIdx.x; v < EDIM / 2; v += blockDim.x) {
            ((__nv_bfloat162*)(g_xh + (size_t)pos * EDIM))[v] = z2;
            ((__nv_bfloat162*)(g_xl + (size_t)pos * EDIM))[v] = z2;
        }
        for (int v = threadIdx.x; v < HDIM / 2; v += blockDim.x) {
            ((float2*)(g_hp + (size_t)pos * HDIM))[v] = make_float2(0.f, 0.f);
            ((__nv_bfloat162*)(g_hph + (size_t)pos * HDIM))[v] = z2;
            ((__nv_bfloat162*)(g_hpl + (size_t)pos * HDIM))[v] = z2;
        }
    }
}

// ---------------- merged weight prep (masks + gru split + fc4 pad zero) ----------------
__device__ __forceinline__ void do_mask(const float* __restrict__ alpha,
                                        const float* __restrict__ w,
                                        int layer, int O, int G, int idx) {
    int g = idx % G;
    int o = (idx / G) % O;
    int a = idx / (G * O);
    const float* al = alpha + (size_t)idx * 6;
    float l0 = al[0], l1 = al[1], l2 = al[2], l3 = al[3], l4 = al[4], l5 = al[5];
    float mx = fmaxf(fmaxf(fmaxf(l0, l1), fmaxf(l2, l3)), fmaxf(l4, l5));
    float e0 = __expf((l0 - mx) * 0.2f);
    float e1 = __expf((l1 - mx) * 0.2f);
    float e2 = __expf((l2 - mx) * 0.2f);
    float e3 = __expf((l3 - mx) * 0.2f);
    float e4 = __expf((l4 - mx) * 0.2f);
    float e5 = __expf((l5 - mx) * 0.2f);
    float inv = __fdividef(1.f, e0 + e1 + e2 + e3 + e4 + e5);
    float m0 = (e0 + e1 + e2) * inv;
    float m1 = (e0 + e3 + e4) * inv;
    float m2 = (e1 + e3 + e5) * inv;
    float m3 = (e2 + e4 + e5) * inv;
    int I = G * 4;
    const float* wr = w + (size_t)o * I + g * 4;
    float v0 = wr[0] * m0, v1 = wr[1] * m1, v2 = wr[2] * m2, v3 = wr[3] * m3;
    __nv_bfloat16 *wh, *wl;
    size_t base;
    if (layer == 3) {
        wh = g_w4h; wl = g_w4l;
        base = ((size_t)a * NPAD4 + o) * I + g * 4;   // padded O stride
    } else {
        wh = (layer == 0) ? g_w1h : (layer == 1) ? g_w2h : g_w3h;
        wl = (layer == 0) ? g_w1l : (layer == 1) ? g_w2l : g_w3l;
        base = ((size_t)a * O + o) * I + g * 4;
    }
    split_bf16(v0, wh[base + 0], wl[base + 0]);
    split_bf16(v1, wh[base + 1], wl[base + 1]);
    split_bf16(v2, wh[base + 2], wl[base + 2]);
    split_bf16(v3, wh[base + 3], wl[base + 3]);
}

#define T1   (AGN*HDIM*(EDIM/4))     // 65536
#define T2   (AGN*HDIM*(HDIM/4))     // 524288
#define T4   (AGN*NAOUT*(HDIM/4))    // 16384
#define NW   (H3*HDIM)               // 786432
#define PADV (AGN*(NPAD4-NAOUT)*HDIM/2) // 229376 bf16 pairs
#define PREP_TOTAL (T1 + 2*T2 + T4 + 2*NW + PADV)

__global__ void prep_kernel(const float* __restrict__ fc1_a, const float* __restrict__ fc1_w,
                            const float* __restrict__ fc2_a, const float* __restrict__ fc2_w,
                            const float* __restrict__ fc3_a, const float* __restrict__ fc3_w,
                            const float* __restrict__ fc4_a, const float* __restrict__ fc4_w,
                            const float* __restrict__ w_ih,  const float* __restrict__ w_hh) {
    int i = blockIdx.x * blockDim.x + threadIdx.x;
    if (i < T1) { do_mask(fc1_a, fc1_w, 0, HDIM, EDIM / 4, i); return; }
    i -= T1;
    if (i < T2) { do_mask(fc2_a, fc2_w, 1, HDIM, HDIM / 4, i); return; }
    i -= T2;
    if (i < T2) { do_mask(fc3_a, fc3_w, 2, HDIM, HDIM / 4, i); return; }
    i -= T2;
    if (i < T4) { do_mask(fc4_a, fc4_w, 3, NAOUT, HDIM / 4, i); return; }
    i -= T4;
    if (i < NW) { split_bf16(w_ih[i], g_wihh[i], g_wihl[i]); return; }
    i -= NW;
    if (i < NW) { split_bf16(w_hh[i], g_whhh[i], g_whhl[i]); return; }
    i -= NW;
    if (i < PADV) {
        const int PR = (NPAD4 - NAOUT) * HDIM / 2;   // pairs per agent
        int a = i / PR;
        int r = i % PR;
        int o = NAOUT + r / (HDIM / 2);
        int k2 = r % (HDIM / 2);
        size_t off = ((size_t)a * NPAD4 + o) * HDIM + k2 * 2;
        __nv_bfloat162 z2 = {__float2bfloat16(0.f), __float2bfloat16(0.f)};
        *(__nv_bfloat162*)(g_w4h + off) = z2;
        *(__nv_bfloat162*)(g_w4l + off) = z2;
    }
}

// ---------------- mma.sync bf16x3 GEMM (3-stage cp.async pipeline) ----------------
// Y[m,n] = X[m,:] . W[agent][n,:] + bias ; X,W as bf16 (hi,lo) pairs.
// CTA tile 128x128, 8 warps of 32(M)x64(N). K chunk = 64, 3 smem stages.
// gruMode: blockIdx.z selects (y1,wih,gi,bias) / (hp,whh,gh,bias2).
// ysel==5: fc4 mode — scatter out_q[perm[m]*16+n] for n<16.
#define STAGE_BYTES 65536
#define NSTAGE 3
#define A_HI 0
#define A_LO 16384
#define B_HI 32768
#define B_LO 49152

__global__ __launch_bounds__(256, 1)
void gemm_tc(int xsel, int wsel, long wStride,
             const float* __restrict__ bias, const float* __restrict__ bias2,
             int ysel, int K, int N, int doRelu, int gruMode,
             float* __restrict__ outq) {
    extern __shared__ char dsm[];

    if (gruMode && blockIdx.z == 1) { xsel = 2; wsel = 4; ysel = 2; bias = bias2; }

    const __nv_bfloat16 *Xh, *Xl, *Wh, *Wl;
    switch (xsel) {
        case 0: Xh = g_xh;  Xl = g_xl;  break;
        case 1: Xh = g_y1h; Xl = g_y1l; break;
        case 2: Xh = g_hph; Xl = g_hpl; break;
        case 3: Xh = g_hnh; Xl = g_hnl; break;
        case 4: Xh = g_q2h; Xl = g_q2l; break;
        default: Xh = g_q3h; Xl = g_q3l; break;
    }
    switch (wsel) {
        case 0: Wh = g_w1h;  Wl = g_w1l;  break;
        case 1: Wh = g_w2h;  Wl = g_w2l;  break;
        case 2: Wh = g_w3h;  Wl = g_w3l;  break;
        case 3: Wh = g_wihh; Wl = g_wihl; break;
        case 4: Wh = g_whhh; Wl = g_whhl; break;
        default: Wh = g_w4h; Wl = g_w4l; break;
    }
    float* Yf = nullptr;
    __nv_bfloat16 *Yh = nullptr, *Yl = nullptr;
    switch (ysel) {
        case 0: Yh = g_y1h; Yl = g_y1l; break;
        case 1: Yf = g_gi; break;
        case 2: Yf = g_gh; break;
        case 3: Yh = g_q2h; Yl = g_q2l; break;
        case 4: Yh = g_q3h; Yl = g_q3l; break;
        default: break; // ysel 5: fc4 scatter
    }

    const int tile_n = blockIdx.x, tile_m = blockIdx.y;
    const int agent = g_tile_agent[tile_m];
    Wh += (size_t)agent * wStride;
    Wl += (size_t)agent * wStride;

    const int tid = threadIdx.x;
    const int wid = tid >> 5;
    const int lane = tid & 31;
    const int warp_m = (wid & 3) * 32;
    const int warp_n = (wid >> 2) * 64;

    uint32_t sb = smem_u32(dsm);
    uint32_t tb = (sb + 1023u) & ~1023u;

    const __nv_bfloat16* srcs[4] = {Xh, Xl, Wh, Wl};
    const int C = K >> 6;

    const uint32_t a_bo0 = (uint32_t)(warp_m + (lane & 15)) * 128 + ((lane >> 4) << 4);
    const uint32_t b_bo0 = (uint32_t)(warp_n + (lane & 7) + ((lane >> 4) << 3)) * 128
                         + (((lane >> 3) & 1) << 4);

    float acc[2][8][4];
#pragma unroll
    for (int mi = 0; mi < 2; mi++)
#pragma unroll
        for (int ni = 0; ni < 8; ni++)
#pragma unroll
            for (int j = 0; j < 4; j++) acc[mi][ni][j] = 0.f;

    auto load_stage = [&](int c) {
        const int s = c % NSTAGE;
        const uint32_t stb = tb + s * STAGE_BYTES;
        const int k0 = c << 6;
#pragma unroll
        for (int t = 0; t < 4; t++) {
            const __nv_bfloat16* src = srcs[t];
            const int row0 = (t < 2) ? tile_m * TM : tile_n * 128;
            const uint32_t tbase = stb + t * 16384;
#pragma unroll
            for (int it = 0; it < 4; it++) {
                int seg = tid + it * 256;
                int row = seg >> 3, sc = seg & 7;
                const void* g = src + (size_t)(row0 + row) * K + k0 + sc * 8;
                uint32_t bo = (uint32_t)(row * 128 + sc * 16);
                cp16(tbase + SWZ(bo), g);
            }
        }
        CP_COMMIT();
    };

    load_stage(0);
    if (C > 1) load_stage(1);

    for (int c = 0; c < C; c++) {
        if (c + 2 < C)      { load_stage(c + 2); CP_WAIT(2); }
        else if (c + 1 < C) { CP_WAIT(1); }
        else                { CP_WAIT(0); }
        __syncthreads();

        const uint32_t stb = tb + (c % NSTAGE) * STAGE_BYTES;
        const uint32_t aHi = stb + A_HI, aLo = stb + A_LO;
        const uint32_t bHi = stb + B_HI, bLo = stb + B_LO;

#pragma unroll
        for (int kk = 0; kk < 4; kk++) {
            uint32_t ah[2][4], al2[2][4], bh[4][4], bl[4][4];
#pragma unroll
            for (int mi = 0; mi < 2; mi++) {
                uint32_t bo = a_bo0 + mi * 2048 + kk * 32;
                uint32_t sw = SWZ(bo);
                ldmat_x4(ah[mi], aHi + sw);
                ldmat_x4(al2[mi], aLo + sw);
            }
#pragma unroll
            for (int pi = 0; pi < 4; pi++) {
                uint32_t bo = b_bo0 + pi * 2048 + kk * 32;
                uint32_t sw = SWZ(bo);
                ldmat_x4(bh[pi], bHi + sw);
                ldmat_x4(bl[pi], bLo + sw);
            }
#pragma unroll
            for (int mi = 0; mi < 2; mi++) {
#pragma unroll
                for (int pi = 0; pi < 4; pi++) {
                    mma16816(acc[mi][pi * 2 + 0], ah[mi],  &bh[pi][0]);
                    mma16816(acc[mi][pi * 2 + 1], ah[mi],  &bh[pi][2]);
                    mma16816(acc[mi][pi * 2 + 0], ah[mi],  &bl[pi][0]);
                    mma16816(acc[mi][pi * 2 + 1], ah[mi],  &bl[pi][2]);
                    mma16816(acc[mi][pi * 2 + 0], al2[mi], &bh[pi][0]);
                    mma16816(acc[mi][pi * 2 + 1], al2[mi], &bh[pi][2]);
                }
            }
        }
        __syncthreads();
    }

    const int g = lane >> 2, tg = lane & 3;

    if (ysel == 5) {
        // fc4: only cols 0..15 are real; scatter via perm.
        if (warp_n != 0) return;
#pragma unroll
        for (int mi = 0; mi < 2; mi++) {
            const int m_lo = tile_m * TM + warp_m + mi * 16 + g;
#pragma unroll
            for (int ni = 0; ni < 2; ni++) {
                const int n = ni * 8 + tg * 2;
                const float b0 = bias[n], b1 = bias[n + 1];
                float* c = acc[mi][ni];
#pragma unroll
                for (int half = 0; half < 2; half++) {
                    const int m = m_lo + half * 8;
                    int dst = g_perm[m];
                    if (dst >= 0) {
                        float2 f2 = make_float2(c[half * 2 + 0] + b0, c[half * 2 + 1] + b1);
                        *(float2*)(outq + (size_t)dst * NAOUT + n) = f2;
                    }
                }
            }
        }
        return;
    }

#pragma unroll
    for (int mi = 0; mi < 2; mi++) {
        const int m_lo = tile_m * TM + warp_m + mi * 16 + g;
#pragma unroll
        for (int ni = 0; ni < 8; ni++) {
            const int n = tile_n * 128 + warp_n + ni * 8 + tg * 2;
            const float b0 = bias[n], b1 = bias[n + 1];
            float* c = acc[mi][ni];
#pragma unroll
            for (int half = 0; half < 2; half++) {
                const int m = m_lo + half * 8;
                float v0 = c[half * 2 + 0] + b0;
                float v1 = c[half * 2 + 1] + b1;
                if (doRelu) { v0 = fmaxf(v0, 0.f); v1 = fmaxf(v1, 0.f); }
                const size_t base = (size_t)m * N + n;
                if (Yf) {
                    *(float2*)(Yf + base) = make_float2(v0, v1);
                } else {
                    __nv_bfloat16 h0, l0, h1, l1;
                    split_bf16(v0, h0, l0);
                    split_bf16(v1, h1, l1);
                    *(__nv_bfloat162*)(Yh + base) = {h0, h1};
                    *(__nv_bfloat162*)(Yl + base) = {l0, l1};
                }
            }
        }
    }
}

// ---------------- GRU gate math (tanh.approx) + scatter of h ----------------
__global__ void gate_kernel(float* __restrict__ out_h) {
    const int JW = HDIM / 4;
    int idx = blockIdx.x * blockDim.x + threadIdx.x;
    if (idx >= MAXP * JW) return;
    int pos = idx / JW;
    int n = g_perm[pos];
    if (n < 0) return;   // padding rows: g_hn stays zero (deterministic)
    int j = (idx % JW) * 4;
    size_t gb = (size_t)pos * H3 + j;
    float4 ir = *(const float4*)(g_gi + gb);
    float4 hr = *(const float4*)(g_gh + gb);
    float4 iz = *(const float4*)(g_gi + gb + HDIM);
    float4 hz = *(const float4*)(g_gh + gb + HDIM);
    float4 in_ = *(const float4*)(g_gi + gb + 2 * HDIM);
    float4 hn_ = *(const float4*)(g_gh + gb + 2 * HDIM);
    float4 hp4 = *(const float4*)(g_hp + (size_t)pos * HDIM + j);

    float irv[4] = {ir.x, ir.y, ir.z, ir.w};
    float hrv[4] = {hr.x, hr.y, hr.z, hr.w};
    float izv[4] = {iz.x, iz.y, iz.z, iz.w};
    float hzv[4] = {hz.x, hz.y, hz.z, hz.w};
    float inv[4] = {in_.x, in_.y, in_.z, in_.w};
    float hnv[4] = {hn_.x, hn_.y, hn_.z, hn_.w};
    float hpv[4] = {hp4.x, hp4.y, hp4.z, hp4.w};
    float hv[4];
    __nv_bfloat16 hh[4], hl[4];
#pragma unroll
    for (int k = 0; k < 4; k++) {
        float r = sigf(irv[k] + hrv[k]);
        float z = sigf(izv[k] + hzv[k]);
        float nn = tfast(inv[k] + r * hnv[k]);
        hv[k] = nn + z * (hpv[k] - nn);
        split_bf16(hv[k], hh[k], hl[k]);
    }
    __nv_bfloat162* hhp = (__nv_bfloat162*)(g_hnh + (size_t)pos * HDIM + j);
    __nv_bfloat162* hlp = (__nv_bfloat162*)(g_hnl + (size_t)pos * HDIM + j);
    hhp[0] = {hh[0], hh[1]}; hhp[1] = {hh[2], hh[3]};
    hlp[0] = {hl[0], hl[1]}; hlp[1] = {hl[2], hl[3]};
    *(float4*)(out_h + (size_t)n * HDIM + j) = make_float4(hv[0], hv[1], hv[2], hv[3]);
}

// ---------------- launch ----------------
extern "C" void kernel_launch(void* const* d_in, const int* in_sizes, int n_in,
                              void* d_out, int out_size) {
    const float* inputs = (const float*)d_in[0];
    const float* hidden = (const float*)d_in[1];
    const int*   ids    = (const int*)d_in[2];
    const float* fc1_w  = (const float*)d_in[3];
    const float* fc1_b  = (const float*)d_in[4];
    const float* fc1_a  = (const float*)d_in[5];
    const float* w_ih   = (const float*)d_in[6];
    const float* w_hh   = (const float*)d_in[7];
    const float* b_ih   = (const float*)d_in[8];
    const float* b_hh   = (const float*)d_in[9];
    const float* fc2_w  = (const float*)d_in[10];
    const float* fc2_b  = (const float*)d_in[11];
    const float* fc2_a  = (const float*)d_in[12];
    const float* fc3_w  = (const float*)d_in[13];
    const float* fc3_b  = (const float*)d_in[14];
    const float* fc3_a  = (const float*)d_in[15];
    const float* fc4_w  = (const float*)d_in[16];
    const float* fc4_b  = (const float*)d_in[17];
    const float* fc4_a  = (const float*)d_in[18];

    float* out   = (float*)d_out;
    float* out_q = out;
    float* out_h = out + (size_t)BA * NAOUT;

    const int SMEM_GEMM = NSTAGE * STAGE_BYTES + 1024;
    cudaFuncSetAttribute(gemm_tc, cudaFuncAttributeMaxDynamicSharedMemorySize, SMEM_GEMM);

    // 1) agent grouping
    init_kernel<<<(MAXP + 255) / 256, 256>>>();
    count_kernel<<<(BA + 255) / 256, 256>>>(ids);
    offsets_kernel<<<1, 32>>>();
    scatter_kernel<<<(BA + 255) / 256, 256>>>(ids);

    // 2) all weight prep in one launch
    prep_kernel<<<(PREP_TOTAL + 255) / 256, 256>>>(
        fc1_a, fc1_w, fc2_a, fc2_w, fc3_a, fc3_w, fc4_a, fc4_w, w_ih, w_hh);

    // 3) gather permuted activations
    gather_kernel<<<MAXP, 128>>>(inputs, hidden);

    // 4) fc1 + relu -> y1 pair
    gemm_tc<<<dim3(HDIM / 128, MTILES), 256, SMEM_GEMM>>>(
        0, 0, (long)HDIM * EDIM, fc1_b, nullptr, 0, EDIM, HDIM, 1, 0, nullptr);

    // 5) GRU GEMMs merged (z=0: gi, z=1: gh)
    gemm_tc<<<dim3(H3 / 128, MTILES, 2), 256, SMEM_GEMM>>>(
        1, 3, 0, b_ih, b_hh, 1, HDIM, H3, 0, 1, nullptr);

    // 6) GRU gates -> hn pair (+ scatter h)
    gate_kernel<<<(MAXP * (HDIM / 4) + 255) / 256, 256>>>(out_h);

    // 7) fc2 + relu -> q2 pair ; fc3 + relu -> q3 pair
    gemm_tc<<<dim3(HDIM / 128, MTILES), 256, SMEM_GEMM>>>(
        3, 1, (long)HDIM * HDIM, fc2_b, nullptr, 3, HDIM, HDIM, 1, 0, nullptr);
    gemm_tc<<<dim3(HDIM / 128, MTILES), 256, SMEM_GEMM>>>(
        4, 2, (long)HDIM * HDIM, fc3_b, nullptr, 4, HDIM, HDIM, 1, 0, nullptr);

    // 8) fc4 via tensor path (+ fused scatter of q)
    gemm_tc<<<dim3(1, MTILES), 256, SMEM_GEMM>>>(
        5, 5, (long)NPAD4 * HDIM, fc4_b, nullptr, 5, HDIM, NPAD4, 0, 0, out_q);
}

// round 11
// speedup vs baseline: 3.2475x; 1.0197x over previous
#include <cuda_runtime.h>
#include <cuda_bf16.h>
#include <cstdint>
#include <math.h>

// ---------------- problem constants ----------------
#define BA    8192
#define AGN   8
#define EDIM  64
#define HDIM  512
#define H3    1536
#define NAOUT 16
#define NPAD4 128      // fc4 N padded to 128
#define TM    128
#define MAXP  9216
#define MTILES (MAXP/TM) // 72

// ---------------- PTX helpers ----------------
__device__ __forceinline__ uint32_t smem_u32(const void* p) {
    uint32_t a;
    asm("{ .reg .u64 t; cvta.to.shared.u64 t, %1; cvt.u32.u64 %0, t; }" : "=r"(a) : "l"(p));
    return a;
}
__device__ __forceinline__ void cp16(uint32_t saddr, const void* g) {
    asm volatile("{ .reg .u64 ga; cvta.to.global.u64 ga, %1;\n\t"
                 "cp.async.cg.shared.global [%0], [ga], 16; }"
                 :: "r"(saddr), "l"(g) : "memory");
}
#define CP_COMMIT() asm volatile("cp.async.commit_group;" ::: "memory")
#define CP_WAIT(n)  asm volatile("cp.async.wait_group %0;" :: "n"(n) : "memory")

__device__ __forceinline__ void ldmat_x4(uint32_t* r, uint32_t addr) {
    asm volatile("ldmatrix.sync.aligned.m8n8.x4.shared.b16 {%0,%1,%2,%3}, [%4];"
        : "=r"(r[0]), "=r"(r[1]), "=r"(r[2]), "=r"(r[3]) : "r"(addr));
}
__device__ __forceinline__ void mma16816(float* c, const uint32_t* a, const uint32_t* b) {
    asm volatile("mma.sync.aligned.m16n8k16.row.col.f32.bf16.bf16.f32 "
        "{%0,%1,%2,%3}, {%4,%5,%6,%7}, {%8,%9}, {%0,%1,%2,%3};"
        : "+f"(c[0]), "+f"(c[1]), "+f"(c[2]), "+f"(c[3])
        : "r"(a[0]), "r"(a[1]), "r"(a[2]), "r"(a[3]), "r"(b[0]), "r"(b[1]));
}
__device__ __forceinline__ float tfast(float x) {
    float y; asm("tanh.approx.f32 %0, %1;" : "=f"(y) : "f"(x)); return y;
}
__device__ __forceinline__ float sigf(float x) { return 0.5f * tfast(0.5f * x) + 0.5f; }

// swizzle for 64-byte rows (Swizzle<2,4,3>): bits [5:4] ^= bits [8:7]
#define SWZ64(bo) ((bo) ^ (((bo) >> 3) & 0x30))

__device__ __forceinline__ void split_bf16(float v, __nv_bfloat16& h, __nv_bfloat16& l) {
    h = __float2bfloat16(v);
    l = __float2bfloat16(v - __bfloat162float(h));
}

// ---------------- scratch (static device memory; no allocs) ----------------
__device__ __nv_bfloat16 g_w1h[AGN*HDIM*EDIM],  g_w1l[AGN*HDIM*EDIM];
__device__ __nv_bfloat16 g_w2h[AGN*HDIM*HDIM],  g_w2l[AGN*HDIM*HDIM];
__device__ __nv_bfloat16 g_w3h[AGN*HDIM*HDIM],  g_w3l[AGN*HDIM*HDIM];
__device__ __nv_bfloat16 g_w4h[AGN*NPAD4*HDIM], g_w4l[AGN*NPAD4*HDIM];
__device__ __nv_bfloat16 g_wihh[H3*HDIM], g_wihl[H3*HDIM];
__device__ __nv_bfloat16 g_whhh[H3*HDIM], g_whhl[H3*HDIM];
__device__ __nv_bfloat16 g_xh [MAXP*EDIM], g_xl [MAXP*EDIM];
__device__ __nv_bfloat16 g_hph[MAXP*HDIM], g_hpl[MAXP*HDIM];
__device__ __nv_bfloat16 g_y1h[MAXP*HDIM], g_y1l[MAXP*HDIM];
__device__ __nv_bfloat16 g_hnh[MAXP*HDIM], g_hnl[MAXP*HDIM];
__device__ __nv_bfloat16 g_q2h[MAXP*HDIM], g_q2l[MAXP*HDIM];
__device__ __nv_bfloat16 g_q3h[MAXP*HDIM], g_q3l[MAXP*HDIM];
__device__ float g_hp [MAXP*HDIM];
__device__ float g_rz [MAXP*1024];   // r,z pre-activation sums
__device__ float g_gi [MAXP*HDIM];   // i_n
__device__ float g_gh [MAXP*HDIM];   // h_n
__device__ int   g_perm[MAXP];
__device__ int   g_counts[AGN];
__device__ int   g_cursor[AGN];
__device__ int   g_segstart[AGN];
__device__ int   g_tile_agent[MTILES];

// ---------------- grouping kernels ----------------
__global__ void init_kernel() {
    int i = blockIdx.x * blockDim.x + threadIdx.x;
    if (i < MAXP) g_perm[i] = -1;
    if (i < AGN) { g_counts[i] = 0; g_cursor[i] = 0; }
}

__global__ void count_kernel(const int* __restrict__ ids) {
    int i = blockIdx.x * blockDim.x + threadIdx.x;
    if (i < BA) atomicAdd(&g_counts[ids[i]], 1);
}

__global__ void offsets_kernel() {
    if (threadIdx.x == 0) {
        int off = 0;
        for (int a = 0; a < AGN; a++) {
            g_segstart[a] = off;
            off += ((g_counts[a] + TM - 1) / TM) * TM;
        }
        for (int t = 0; t < MTILES; t++) {
            int r = t * TM;
            int ag = 0;
            for (int a = 1; a < AGN; a++)
                if (r >= g_segstart[a]) ag = a;
            g_tile_agent[t] = ag;
        }
    }
}

__global__ void scatter_kernel(const int* __restrict__ ids) {
    int i = blockIdx.x * blockDim.x + threadIdx.x;
    if (i < BA) {
        int a = ids[i];
        int pos = g_segstart[a] + atomicAdd(&g_cursor[a], 1);
        g_perm[pos] = i;
    }
}

__global__ void gather_kernel(const float* __restrict__ x, const float* __restrict__ h) {
    int pos = blockIdx.x;
    int n = g_perm[pos];
    if (n >= 0) {
        for (int v = threadIdx.x; v < EDIM / 4; v += blockDim.x) {
            float4 f = *(const float4*)(x + (size_t)n * EDIM + v * 4);
            __nv_bfloat16 h0, l0, h1, l1, h2, l2, h3, l3;
            split_bf16(f.x, h0, l0); split_bf16(f.y, h1, l1);
            split_bf16(f.z, h2, l2); split_bf16(f.w, h3, l3);
            __nv_bfloat162* xhp = (__nv_bfloat162*)(g_xh + (size_t)pos * EDIM + v * 4);
            __nv_bfloat162* xlp = (__nv_bfloat162*)(g_xl + (size_t)pos * EDIM + v * 4);
            xhp[0] = {h0, h1}; xhp[1] = {h2, h3};
            xlp[0] = {l0, l1}; xlp[1] = {l2, l3};
        }
        for (int v = threadIdx.x; v < HDIM / 4; v += blockDim.x) {
            float4 f = *(const float4*)(h + (size_t)n * HDIM + v * 4);
            *(float4*)(g_hp + (size_t)pos * HDIM + v * 4) = f;
            __nv_bfloat16 h0, l0, h1, l1, h2, l2, h3, l3;
            split_bf16(f.x, h0, l0); split_bf16(f.y, h1, l1);
            split_bf16(f.z, h2, l2); split_bf16(f.w, h3, l3);
            __nv_bfloat162* hhp = (__nv_bfloat162*)(g_hph + (size_t)pos * HDIM + v * 4);
            __nv_bfloat162* hlp = (__nv_bfloat162*)(g_hpl + (size_t)pos * HDIM + v * 4);
            hhp[0] = {h0, h1}; hhp[1] = {h2, h3};
            hlp[0] = {l0, l1}; hlp[1] = {l2, l3};
        }
    } else {
        __nv_bfloat162 z2 = {__float2bfloat16(0.f), __float2bfloat16(0.f)};
        for (int v = threadIdx.x; v < EDIM / 2; v += blockDim.x) {
            ((__nv_bfloat162*)(g_xh + (size_t)pos * EDIM))[v] = z2;
            ((__nv_bfloat162*)(g_xl + (size_t)pos * EDIM))[v] = z2;
        }
        for (int v = threadIdx.x; v < HDIM / 2; v += blockDim.x) {
            ((float2*)(g_hp + (size_t)pos * HDIM))[v] = make_float2(0.f, 0.f);
            ((__nv_bfloat162*)(g_hph + (size_t)pos * HDIM))[v] = z2;
            ((__nv_bfloat162*)(g_hpl + (size_t)pos * HDIM))[v] = z2;
        }
    }
}

// ---------------- merged weight prep ----------------
__device__ __forceinline__ void do_mask(const float* __restrict__ alpha,
                                        const float* __restrict__ w,
                                        int layer, int O, int G, int idx) {
    int g = idx % G;
    int o = (idx / G) % O;
    int a = idx / (G * O);
    const float* al = alpha + (size_t)idx * 6;
    float l0 = al[0], l1 = al[1], l2 = al[2], l3 = al[3], l4 = al[4], l5 = al[5];
    float mx = fmaxf(fmaxf(fmaxf(l0, l1), fmaxf(l2, l3)), fmaxf(l4, l5));
    float e0 = __expf((l0 - mx) * 0.2f);
    float e1 = __expf((l1 - mx) * 0.2f);
    float e2 = __expf((l2 - mx) * 0.2f);
    float e3 = __expf((l3 - mx) * 0.2f);
    float e4 = __expf((l4 - mx) * 0.2f);
    float e5 = __expf((l5 - mx) * 0.2f);
    float inv = __fdividef(1.f, e0 + e1 + e2 + e3 + e4 + e5);
    float m0 = (e0 + e1 + e2) * inv;
    float m1 = (e0 + e3 + e4) * inv;
    float m2 = (e1 + e3 + e5) * inv;
    float m3 = (e2 + e4 + e5) * inv;
    int I = G * 4;
    const float* wr = w + (size_t)o * I + g * 4;
    float v0 = wr[0] * m0, v1 = wr[1] * m1, v2 = wr[2] * m2, v3 = wr[3] * m3;
    __nv_bfloat16 *wh, *wl;
    size_t base;
    if (layer == 3) {
        wh = g_w4h; wl = g_w4l;
        base = ((size_t)a * NPAD4 + o) * I + g * 4;
    } else {
        wh = (layer == 0) ? g_w1h : (layer == 1) ? g_w2h : g_w3h;
        wl = (layer == 0) ? g_w1l : (layer == 1) ? g_w2l : g_w3l;
        base = ((size_t)a * O + o) * I + g * 4;
    }
    split_bf16(v0, wh[base + 0], wl[base + 0]);
    split_bf16(v1, wh[base + 1], wl[base + 1]);
    split_bf16(v2, wh[base + 2], wl[base + 2]);
    split_bf16(v3, wh[base + 3], wl[base + 3]);
}

#define T1   (AGN*HDIM*(EDIM/4))
#define T2   (AGN*HDIM*(HDIM/4))
#define T4   (AGN*NAOUT*(HDIM/4))
#define NW   (H3*HDIM)
#define PADV (AGN*(NPAD4-NAOUT)*HDIM/2)
#define PREP_TOTAL (T1 + 2*T2 + T4 + 2*NW + PADV)

__global__ void prep_kernel(const float* __restrict__ fc1_a, const float* __restrict__ fc1_w,
                            const float* __restrict__ fc2_a, const float* __restrict__ fc2_w,
                            const float* __restrict__ fc3_a, const float* __restrict__ fc3_w,
                            const float* __restrict__ fc4_a, const float* __restrict__ fc4_w,
                            const float* __restrict__ w_ih,  const float* __restrict__ w_hh) {
    int i = blockIdx.x * blockDim.x + threadIdx.x;
    if (i < T1) { do_mask(fc1_a, fc1_w, 0, HDIM, EDIM / 4, i); return; }
    i -= T1;
    if (i < T2) { do_mask(fc2_a, fc2_w, 1, HDIM, HDIM / 4, i); return; }
    i -= T2;
    if (i < T2) { do_mask(fc3_a, fc3_w, 2, HDIM, HDIM / 4, i); return; }
    i -= T2;
    if (i < T4) { do_mask(fc4_a, fc4_w, 3, NAOUT, HDIM / 4, i); return; }
    i -= T4;
    if (i < NW) { split_bf16(w_ih[i], g_wihh[i], g_wihl[i]); return; }
    i -= NW;
    if (i < NW) { split_bf16(w_hh[i], g_whhh[i], g_whhl[i]); return; }
    i -= NW;
    if (i < PADV) {
        const int PR = (NPAD4 - NAOUT) * HDIM / 2;
        int a = i / PR;
        int r = i % PR;
        int o = NAOUT + r / (HDIM / 2);
        int k2 = r % (HDIM / 2);
        size_t off = ((size_t)a * NPAD4 + o) * HDIM + k2 * 2;
        __nv_bfloat162 z2 = {__float2bfloat16(0.f), __float2bfloat16(0.f)};
        *(__nv_bfloat162*)(g_w4h + off) = z2;
        *(__nv_bfloat162*)(g_w4l + off) = z2;
    }
}

// ---------------- mma.sync bf16x3 GEMM ----------------
// K-chunk 32 (64B rows, SWZ64), 3 cp.async stages (96KB), 2 CTAs/SM.
// special: 0 = normal, 1 = GRU rz (A=[y1|hp], B=[wih|whh] rows 0..1023, dual bias),
//          2 = GRU n-gates (z=0: y1 x wih[1024:], z=1: hp x whh[1024:]),
//          3 = fc4 scatter epilogue.
#define KC 32
#define TILE_BYTES 8192          // 128 rows x 64 B
#define STAGE_BYTES 32768        // 4 tiles
#define NSTAGE 3
#define A_HI 0
#define A_LO 8192
#define B_HI 16384
#define B_LO 24576

__global__ __launch_bounds__(256, 2)
void gemm_tc(int special, int xsel, int wsel, long wStride,
             const float* __restrict__ bias, const float* __restrict__ bias2,
             int ysel, int K, int N, int doRelu, float* __restrict__ outq) {
    extern __shared__ char dsm[];

    const __nv_bfloat16 *Xh = nullptr, *Xl = nullptr, *Wh = nullptr, *Wl = nullptr;
    float* Yf = nullptr;
    __nv_bfloat16 *Yh = nullptr, *Yl = nullptr;
    const float* biasAdd = nullptr;   // dual-bias (rz mode)

    if (special == 2) {
        if (blockIdx.z == 0) { Xh = g_y1h; Xl = g_y1l; Wh = g_wihh + (size_t)1024 * HDIM; Wl = g_wihl + (size_t)1024 * HDIM; Yf = g_gi; }
        else                 { Xh = g_hph; Xl = g_hpl; Wh = g_whhh + (size_t)1024 * HDIM; Wl = g_whhl + (size_t)1024 * HDIM; Yf = g_gh; bias = bias2; }
    } else if (special == 1) {
        Yf = g_rz; biasAdd = bias2;
    } else {
        switch (xsel) {
            case 0: Xh = g_xh;  Xl = g_xl;  break;
            case 3: Xh = g_hnh; Xl = g_hnl; break;
            case 4: Xh = g_q2h; Xl = g_q2l; break;
            default: Xh = g_q3h; Xl = g_q3l; break;
        }
        switch (wsel) {
            case 0: Wh = g_w1h;  Wl = g_w1l;  break;
            case 1: Wh = g_w2h;  Wl = g_w2l;  break;
            case 2: Wh = g_w3h;  Wl = g_w3l;  break;
            default: Wh = g_w4h; Wl = g_w4l; break;
        }
        switch (ysel) {
            case 0: Yh = g_y1h; Yl = g_y1l; break;
            case 3: Yh = g_q2h; Yl = g_q2l; break;
            case 4: Yh = g_q3h; Yl = g_q3l; break;
            default: break; // ysel 5 (fc4)
        }
        const int agent = g_tile_agent[blockIdx.y];
        Wh += (size_t)agent * wStride;
        Wl += (size_t)agent * wStride;
    }

    const int tile_n = blockIdx.x, tile_m = blockIdx.y;
    const int tid = threadIdx.x;
    const int wid = tid >> 5;
    const int lane = tid & 31;
    const int warp_m = (wid & 3) * 32;
    const int warp_n = (wid >> 2) * 64;

    uint32_t sb = smem_u32(dsm);
    uint32_t tb = (sb + 1023u) & ~1023u;

    const int C = K / KC;

    const uint32_t a_bo0 = (uint32_t)(warp_m + (lane & 15)) * 64 + ((lane >> 4) << 4);
    const uint32_t b_bo0 = (uint32_t)(warp_n + (lane & 7) + ((lane >> 4) << 3)) * 64
                         + (((lane >> 3) & 1) << 4);

    float acc[2][8][4];
#pragma unroll
    for (int mi = 0; mi < 2; mi++)
#pragma unroll
        for (int ni = 0; ni < 8; ni++)
#pragma unroll
            for (int j = 0; j < 4; j++) acc[mi][ni][j] = 0.f;

    auto load_stage = [&](int c) {
        const int s = c % NSTAGE;
        const uint32_t stb = tb + s * STAGE_BYTES;
        const int k0 = c * KC;
        const __nv_bfloat16 *sAh, *sAl, *sBh, *sBl;
        int ka, strA, strB;
        if (special == 1) {
            if (k0 < HDIM) { sAh = g_y1h; sAl = g_y1l; sBh = g_wihh; sBl = g_wihl; ka = k0; }
            else           { sAh = g_hph; sAl = g_hpl; sBh = g_whhh; sBl = g_whhl; ka = k0 - HDIM; }
            strA = HDIM; strB = HDIM;
        } else {
            sAh = Xh; sAl = Xl; sBh = Wh; sBl = Wl; ka = k0; strA = K; strB = K;
        }
        // 4 tiles of 128 rows x 32 bf16 (64B); 512 16B segs per tile, 2 per thread
        const __nv_bfloat16* srcs[4] = {sAh, sAl, sBh, sBl};
#pragma unroll
        for (int t = 0; t < 4; t++) {
            const __nv_bfloat16* src = srcs[t];
            const int row0 = (t < 2) ? tile_m * TM : tile_n * 128;
            const int str  = (t < 2) ? strA : strB;
            const uint32_t tbase = stb + t * TILE_BYTES;
#pragma unroll
            for (int it = 0; it < 2; it++) {
                int seg = tid + it * 256;
                int row = seg >> 2, sc = seg & 3;
                const void* g = src + (size_t)(row0 + row) * str + ka + sc * 8;
                uint32_t bo = (uint32_t)(row * 64 + sc * 16);
                cp16(tbase + SWZ64(bo), g);
            }
        }
        CP_COMMIT();
    };

    load_stage(0);
    if (C > 1) load_stage(1);

    for (int c = 0; c < C; c++) {
        if (c + 2 < C)      { load_stage(c + 2); CP_WAIT(2); }
        else if (c + 1 < C) { CP_WAIT(1); }
        else                { CP_WAIT(0); }
        __syncthreads();

        const uint32_t stb = tb + (c % NSTAGE) * STAGE_BYTES;

#pragma unroll
        for (int kk = 0; kk < 2; kk++) {
            uint32_t ah[2][4], al2[2][4];
#pragma unroll
            for (int mi = 0; mi < 2; mi++) {
                uint32_t sw = SWZ64(a_bo0 + mi * 1024 + kk * 32);
                ldmat_x4(ah[mi],  stb + A_HI + sw);
                ldmat_x4(al2[mi], stb + A_LO + sw);
            }
#pragma unroll
            for (int pi = 0; pi < 4; pi++) {
                uint32_t bh[4], bl[4];
                uint32_t sw = SWZ64(b_bo0 + pi * 1024 + kk * 32);
                ldmat_x4(bh, stb + B_HI + sw);
                ldmat_x4(bl, stb + B_LO + sw);
#pragma unroll
                for (int mi = 0; mi < 2; mi++) {
                    mma16816(acc[mi][pi * 2 + 0], ah[mi],  &bh[0]);
                    mma16816(acc[mi][pi * 2 + 1], ah[mi],  &bh[2]);
                    mma16816(acc[mi][pi * 2 + 0], ah[mi],  &bl[0]);
                    mma16816(acc[mi][pi * 2 + 1], ah[mi],  &bl[2]);
                    mma16816(acc[mi][pi * 2 + 0], al2[mi], &bh[0]);
                    mma16816(acc[mi][pi * 2 + 1], al2[mi], &bh[2]);
                }
            }
        }
        __syncthreads();
    }

    const int g = lane >> 2, tg = lane & 3;

    if (special == 3) {
        if (warp_n != 0) return;
#pragma unroll
        for (int mi = 0; mi < 2; mi++) {
            const int m_lo = tile_m * TM + warp_m + mi * 16 + g;
#pragma unroll
            for (int ni = 0; ni < 2; ni++) {
                const int n = ni * 8 + tg * 2;
                const float b0 = bias[n], b1 = bias[n + 1];
                float* c = acc[mi][ni];
#pragma unroll
                for (int half = 0; half < 2; half++) {
                    const int m = m_lo + half * 8;
                    int dst = g_perm[m];
                    if (dst >= 0) {
                        float2 f2 = make_float2(c[half * 2 + 0] + b0, c[half * 2 + 1] + b1);
                        *(float2*)(outq + (size_t)dst * NAOUT + n) = f2;
                    }
                }
            }
        }
        return;
    }

#pragma unroll
    for (int mi = 0; mi < 2; mi++) {
        const int m_lo = tile_m * TM + warp_m + mi * 16 + g;
#pragma unroll
        for (int ni = 0; ni < 8; ni++) {
            const int n = tile_n * 128 + warp_n + ni * 8 + tg * 2;
            float b0 = bias[n], b1 = bias[n + 1];
            if (biasAdd) { b0 += biasAdd[n]; b1 += biasAdd[n + 1]; }
            float* c = acc[mi][ni];
#pragma unroll
            for (int half = 0; half < 2; half++) {
                const int m = m_lo + half * 8;
                float v0 = c[half * 2 + 0] + b0;
                float v1 = c[half * 2 + 1] + b1;
                if (doRelu) { v0 = fmaxf(v0, 0.f); v1 = fmaxf(v1, 0.f); }
                const size_t base = (size_t)m * N + n;
                if (Yf) {
                    *(float2*)(Yf + base) = make_float2(v0, v1);
                } else {
                    __nv_bfloat16 h0, l0, h1, l1;
                    split_bf16(v0, h0, l0);
                    split_bf16(v1, h1, l1);
                    *(__nv_bfloat162*)(Yh + base) = {h0, h1};
                    *(__nv_bfloat162*)(Yl + base) = {l0, l1};
                }
            }
        }
    }
}

// ---------------- GRU gate math + scatter of h ----------------
__global__ void gate_kernel(float* __restrict__ out_h) {
    const int JW = HDIM / 4;
    int idx = blockIdx.x * blockDim.x + threadIdx.x;
    if (idx >= MAXP * JW) return;
    int pos = idx / JW;
    int n = g_perm[pos];
    if (n < 0) return;
    int j = (idx % JW) * 4;
    float4 rv = *(const float4*)(g_rz + (size_t)pos * 1024 + j);
    float4 zv = *(const float4*)(g_rz + (size_t)pos * 1024 + HDIM + j);
    float4 in4 = *(const float4*)(g_gi + (size_t)pos * HDIM + j);
    float4 hn4 = *(const float4*)(g_gh + (size_t)pos * HDIM + j);
    float4 hp4 = *(const float4*)(g_hp + (size_t)pos * HDIM + j);

    float rvv[4] = {rv.x, rv.y, rv.z, rv.w};
    float zvv[4] = {zv.x, zv.y, zv.z, zv.w};
    float inv[4] = {in4.x, in4.y, in4.z, in4.w};
    float hnv[4] = {hn4.x, hn4.y, hn4.z, hn4.w};
    float hpv[4] = {hp4.x, hp4.y, hp4.z, hp4.w};
    float hv[4];
    __nv_bfloat16 hh[4], hl[4];
#pragma unroll
    for (int k = 0; k < 4; k++) {
        float r = sigf(rvv[k]);
        float z = sigf(zvv[k]);
        float nn = tfast(inv[k] + r * hnv[k]);
        hv[k] = nn + z * (hpv[k] - nn);
        split_bf16(hv[k], hh[k], hl[k]);
    }
    __nv_bfloat162* hhp = (__nv_bfloat162*)(g_hnh + (size_t)pos * HDIM + j);
    __nv_bfloat162* hlp = (__nv_bfloat162*)(g_hnl + (size_t)pos * HDIM + j);
    hhp[0] = {hh[0], hh[1]}; hhp[1] = {hh[2], hh[3]};
    hlp[0] = {hl[0], hl[1]}; hlp[1] = {hl[2], hl[3]};
    *(float4*)(out_h + (size_t)n * HDIM + j) = make_float4(hv[0], hv[1], hv[2], hv[3]);
}

// ---------------- launch ----------------
extern "C" void kernel_launch(void* const* d_in, const int* in_sizes, int n_in,
                              void* d_out, int out_size) {
    const float* inputs = (const float*)d_in[0];
    const float* hidden = (const float*)d_in[1];
    const int*   ids    = (const int*)d_in[2];
    const float* fc1_w  = (const float*)d_in[3];
    const float* fc1_b  = (const float*)d_in[4];
    const float* fc1_a  = (const float*)d_in[5];
    const float* w_ih   = (const float*)d_in[6];
    const float* w_hh   = (const float*)d_in[7];
    const float* b_ih   = (const float*)d_in[8];
    const float* b_hh   = (const float*)d_in[9];
    const float* fc2_w  = (const float*)d_in[10];
    const float* fc2_b  = (const float*)d_in[11];
    const float* fc2_a  = (const float*)d_in[12];
    const float* fc3_w  = (const float*)d_in[13];
    const float* fc3_b  = (const float*)d_in[14];
    const float* fc3_a  = (const float*)d_in[15];
    const float* fc4_w  = (const float*)d_in[16];
    const float* fc4_b  = (const float*)d_in[17];
    const float* fc4_a  = (const float*)d_in[18];

    float* out   = (float*)d_out;
    float* out_q = out;
    float* out_h = out + (size_t)BA * NAOUT;

    const int SMEM_GEMM = NSTAGE * STAGE_BYTES + 1024;
    cudaFuncSetAttribute(gemm_tc, cudaFuncAttributeMaxDynamicSharedMemorySize, SMEM_GEMM);

    // 1) agent grouping
    init_kernel<<<(MAXP + 255) / 256, 256>>>();
    count_kernel<<<(BA + 255) / 256, 256>>>(ids);
    offsets_kernel<<<1, 32>>>();
    scatter_kernel<<<(BA + 255) / 256, 256>>>(ids);

    // 2) weight prep (single launch)
    prep_kernel<<<(PREP_TOTAL + 255) / 256, 256>>>(
        fc1_a, fc1_w, fc2_a, fc2_w, fc3_a, fc3_w, fc4_a, fc4_w, w_ih, w_hh);

    // 3) gather permuted activations
    gather_kernel<<<MAXP, 128>>>(inputs, hidden);

    // 4) fc1 + relu -> y1 pair
    gemm_tc<<<dim3(HDIM / 128, MTILES), 256, SMEM_GEMM>>>(
        0, 0, 0, (long)HDIM * EDIM, fc1_b, nullptr, 0, EDIM, HDIM, 1, nullptr);

    // 5a) GRU r,z sums: [y1|hp] @ [wih|whh rows 0:1024]^T, K=1024, dual bias
    gemm_tc<<<dim3(1024 / 128, MTILES), 256, SMEM_GEMM>>>(
        1, 0, 0, 0, b_ih, b_hh, 6, 1024, 1024, 0, nullptr);

    // 5b) GRU n gates: z=0 -> i_n, z=1 -> h_n
    gemm_tc<<<dim3(HDIM / 128, MTILES, 2), 256, SMEM_GEMM>>>(
        2, 0, 0, 0, b_ih + 1024, b_hh + 1024, 1, HDIM, HDIM, 0, nullptr);

    // 6) GRU gates -> hn pair (+ scatter h)
    gate_kernel<<<(MAXP * (HDIM / 4) + 255) / 256, 256>>>(out_h);

    // 7) fc2 + relu ; fc3 + relu
    gemm_tc<<<dim3(HDIM / 128, MTILES), 256, SMEM_GEMM>>>(
        0, 3, 1, (long)HDIM * HDIM, fc2_b, nullptr, 3, HDIM, HDIM, 1, nullptr);
    gemm_tc<<<dim3(HDIM / 128, MTILES), 256, SMEM_GEMM>>>(
        0, 4, 2, (long)HDIM * HDIM, fc3_b, nullptr, 4, HDIM, HDIM, 1, nullptr);

    // 8) fc4 (+ fused scatter of q)
    gemm_tc<<<dim3(1, MTILES), 256, SMEM_GEMM>>>(
        3, 5, 5, (long)NPAD4 * HDIM, fc4_b, nullptr, 5, HDIM, NPAD4, 0, out_q);
}